// round 1
// baseline (speedup 1.0000x reference)
#include <cuda_runtime.h>
#include <cstdint>

#define BB 8192
#define DD 512
#define CC 80
#define MARGIN 0.3f

#define BM 128
#define BN 128
#define BK 16

// ---- device scratch (no allocations allowed) ----
__device__ float g_e[BB * DD];                 // normalized embeddings (16 MB)
__device__ float g_sq[BB];                     // row |e|^2 after normalize
__device__ unsigned long long g_m0[BB];        // label bits 0..63
__device__ unsigned long long g_m1[BB];        // label bits 64..79
__device__ float g_dist[(size_t)BB * BB];      // pairwise distances (256 MB)
__device__ unsigned g_hardneg[BB];             // float bits, min over negatives
__device__ float g_loss_sum;
__device__ float g_valid_cnt;

// ---- 1) reset accumulators + build label bitmasks ----
__global__ void prep_kernel(const float* __restrict__ labels) {
    int i = blockIdx.x * blockDim.x + threadIdx.x;
    if (i == 0) { g_loss_sum = 0.f; g_valid_cnt = 0.f; }
    if (i < BB) {
        const float* lr = labels + (size_t)i * CC;
        unsigned long long m0 = 0ull, m1 = 0ull;
        #pragma unroll
        for (int c = 0; c < 64; c++)
            if (lr[c] != 0.f) m0 |= (1ull << c);
        #pragma unroll
        for (int c = 64; c < CC; c++)
            if (lr[c] != 0.f) m1 |= (1ull << (c - 64));
        g_m0[i] = m0;
        g_m1[i] = m1;
        g_hardneg[i] = __float_as_uint(1e9f);
    }
}

// ---- 2) L2-normalize rows, record |e|^2 ----
__global__ __launch_bounds__(128) void normalize_kernel(const float* __restrict__ emb) {
    int row = blockIdx.x;
    int t = threadIdx.x;                         // 128 threads, DD/4 = 128 float4
    const float4* in = (const float4*)(emb + (size_t)row * DD);
    float4* out = (float4*)(g_e + (size_t)row * DD);
    float4 v = in[t];
    float ss = v.x * v.x + v.y * v.y + v.z * v.z + v.w * v.w;
    #pragma unroll
    for (int o = 16; o > 0; o >>= 1) ss += __shfl_xor_sync(0xFFFFFFFFu, ss, o);
    __shared__ float red[4];
    if ((t & 31) == 0) red[t >> 5] = ss;
    __syncthreads();
    float tot = red[0] + red[1] + red[2] + red[3];
    float inv = 1.f / fmaxf(sqrtf(tot), 1e-12f);
    v.x *= inv; v.y *= inv; v.z *= inv; v.w *= inv;
    out[t] = v;
    if (t == 0) g_sq[row] = tot * inv * inv;
}

// ---- 3) Gram GEMM (NT, both operands row-major) + fused epilogue:
//         dist = sqrt(max(sq_i+sq_j-2*dot,0)), stored to g_dist,
//         hard-negative partial row-min via atomicMin ----
__global__ __launch_bounds__(256, 1) void gemm_epi_kernel() {
    __shared__ float As[BK][BM];
    __shared__ float Bs[BK][BN];
    __shared__ float s_sqi[BM], s_sqj[BN];
    __shared__ unsigned long long s_mi0[BM], s_mi1[BM], s_mj0[BN], s_mj1[BN];

    const int bx = blockIdx.x;   // j tile
    const int by = blockIdx.y;   // i tile
    const int tid = threadIdx.x;
    const int tx = tid & 15;
    const int ty = tid >> 4;

    const float* Aptr = g_e + (size_t)by * BM * DD;
    const float* Bptr = g_e + (size_t)bx * BN * DD;

    const int lrow = tid >> 2;          // 0..63
    const int lcol = (tid & 3) << 2;    // 0,4,8,12

    float acc[8][8];
    #pragma unroll
    for (int a = 0; a < 8; a++)
        #pragma unroll
        for (int b = 0; b < 8; b++) acc[a][b] = 0.f;

    for (int k0 = 0; k0 < DD; k0 += BK) {
        float4 a0 = *(const float4*)(Aptr + (size_t)lrow * DD + k0 + lcol);
        float4 a1 = *(const float4*)(Aptr + (size_t)(lrow + 64) * DD + k0 + lcol);
        float4 b0 = *(const float4*)(Bptr + (size_t)lrow * DD + k0 + lcol);
        float4 b1 = *(const float4*)(Bptr + (size_t)(lrow + 64) * DD + k0 + lcol);
        __syncthreads();
        As[lcol + 0][lrow] = a0.x; As[lcol + 1][lrow] = a0.y;
        As[lcol + 2][lrow] = a0.z; As[lcol + 3][lrow] = a0.w;
        As[lcol + 0][lrow + 64] = a1.x; As[lcol + 1][lrow + 64] = a1.y;
        As[lcol + 2][lrow + 64] = a1.z; As[lcol + 3][lrow + 64] = a1.w;
        Bs[lcol + 0][lrow] = b0.x; Bs[lcol + 1][lrow] = b0.y;
        Bs[lcol + 2][lrow] = b0.z; Bs[lcol + 3][lrow] = b0.w;
        Bs[lcol + 0][lrow + 64] = b1.x; Bs[lcol + 1][lrow + 64] = b1.y;
        Bs[lcol + 2][lrow + 64] = b1.z; Bs[lcol + 3][lrow + 64] = b1.w;
        __syncthreads();
        #pragma unroll
        for (int k = 0; k < BK; k++) {
            float ar[8], br[8];
            *(float4*)(ar)     = *(const float4*)(&As[k][ty * 8]);
            *(float4*)(ar + 4) = *(const float4*)(&As[k][ty * 8 + 4]);
            *(float4*)(br)     = *(const float4*)(&Bs[k][tx * 8]);
            *(float4*)(br + 4) = *(const float4*)(&Bs[k][tx * 8 + 4]);
            #pragma unroll
            for (int ii = 0; ii < 8; ii++)
                #pragma unroll
                for (int jj = 0; jj < 8; jj++)
                    acc[ii][jj] = fmaf(ar[ii], br[jj], acc[ii][jj]);
        }
    }

    // stage per-row/col metadata
    __syncthreads();
    if (tid < 128) {
        int gi = by * BM + tid;
        int gj = bx * BN + tid;
        s_sqi[tid] = g_sq[gi];
        s_sqj[tid] = g_sq[gj];
        s_mi0[tid] = g_m0[gi]; s_mi1[tid] = g_m1[gi];
        s_mj0[tid] = g_m0[gj]; s_mj1[tid] = g_m1[gj];
    }
    __syncthreads();

    #pragma unroll
    for (int ii = 0; ii < 8; ii++) {
        int li = ty * 8 + ii;
        int gi = by * BM + li;
        float sqi = s_sqi[li];
        unsigned long long mi0 = s_mi0[li], mi1 = s_mi1[li];
        float rmin = 1e9f;
        float dv[8];
        #pragma unroll
        for (int jj = 0; jj < 8; jj++) {
            int lj = tx * 8 + jj;
            float d2 = sqi + s_sqj[lj] - 2.f * acc[ii][jj];
            float d = sqrtf(fmaxf(d2, 0.f));
            dv[jj] = d;
            int inter = __popcll(mi0 & s_mj0[lj]) + __popcll(mi1 & s_mj1[lj]);
            if (inter == 0) rmin = fminf(rmin, d);
        }
        float* gp = g_dist + (size_t)gi * BB + bx * BN + tx * 8;
        *(float4*)(gp)     = make_float4(dv[0], dv[1], dv[2], dv[3]);
        *(float4*)(gp + 4) = make_float4(dv[4], dv[5], dv[6], dv[7]);
        if (rmin < 1e9f)
            atomicMin(&g_hardneg[gi], __float_as_uint(rmin));
    }
}

// ---- 4) per-row weighted hinge over positives ----
__global__ __launch_bounds__(256) void rowloss_kernel() {
    const int i = blockIdx.x;
    const int t = threadIdx.x;
    const float h = __uint_as_float(g_hardneg[i]);
    const unsigned long long mi0 = g_m0[i], mi1 = g_m1[i];
    const float si = (float)(__popcll(mi0) + __popcll(mi1));
    const float* drow = g_dist + (size_t)i * BB;

    float acc = 0.f;
    int cnt = 0;
    int anyneg = 0;
    for (int j = t; j < BB; j += 256) {
        float d = drow[j];
        unsigned long long mj0 = g_m0[j], mj1 = g_m1[j];
        int inter = __popcll(mi0 & mj0) + __popcll(mi1 & mj1);
        if (inter == 0) {
            anyneg = 1;
        } else if (j != i) {
            float sj = (float)(__popcll(mj0) + __popcll(mj1));
            float jac = (float)inter / (si + sj - (float)inter + 1e-8f);
            acc += fmaxf(d - h + MARGIN, 0.f) * jac;
            cnt++;
        }
    }
    #pragma unroll
    for (int o = 16; o > 0; o >>= 1) {
        acc += __shfl_xor_sync(0xFFFFFFFFu, acc, o);
        cnt += __shfl_xor_sync(0xFFFFFFFFu, cnt, o);
        anyneg |= __shfl_xor_sync(0xFFFFFFFFu, anyneg, o);
    }
    __shared__ float sacc[8];
    __shared__ int scnt[8], sneg[8];
    if ((t & 31) == 0) { sacc[t >> 5] = acc; scnt[t >> 5] = cnt; sneg[t >> 5] = anyneg; }
    __syncthreads();
    if (t == 0) {
        float a = 0.f; int c = 0, n = 0;
        #pragma unroll
        for (int w = 0; w < 8; w++) { a += sacc[w]; c += scnt[w]; n |= sneg[w]; }
        if (c > 0 && n) {
            atomicAdd(&g_loss_sum, a / (float)c);
            atomicAdd(&g_valid_cnt, 1.f);
        }
    }
}

// ---- 5) finalize ----
__global__ void finalize_kernel(float* out, int n) {
    if (threadIdx.x == 0 && blockIdx.x == 0) {
        out[0] = g_loss_sum / (g_valid_cnt + 1e-8f);
        for (int k = 1; k < n; k++) out[k] = 0.f;
    }
}

extern "C" void kernel_launch(void* const* d_in, const int* in_sizes, int n_in,
                              void* d_out, int out_size) {
    const float* emb = (const float*)d_in[0];
    const float* labels = (const float*)d_in[1];

    prep_kernel<<<(BB + 255) / 256, 256>>>(labels);
    normalize_kernel<<<BB, 128>>>(emb);
    dim3 grid(BB / BN, BB / BM);
    gemm_epi_kernel<<<grid, 256>>>();
    rowloss_kernel<<<BB, 256>>>();
    finalize_kernel<<<1, 32>>>((float*)d_out, out_size);
}

// round 2
// speedup vs baseline: 1.5042x; 1.5042x over previous
#include <cuda_runtime.h>
#include <cstdint>
#include <math.h>

#define BB 8192
#define DD 512
#define CC 80
#define MARGIN 0.3f

#define BM 128
#define BN 128
#define BK 16
#define NTILE (BB / BM)                 // 64
#define NTRI  (NTILE * (NTILE + 1) / 2) // 2080

// ---- device scratch (no allocations allowed) ----
__device__ float g_e[BB * DD];                 // normalized embeddings (16 MB)
__device__ float g_sq[BB];                     // row |e|^2 after normalize
__device__ ulonglong2 g_m[BB];                 // label bitmask (lo 64, hi 16)
__device__ float g_s[BB];                      // label popcount as float
__device__ float g_dist[(size_t)BB * BB];      // pairwise distances (256 MB)
__device__ unsigned g_hardneg[BB];             // float bits, min over negatives
__device__ float g_loss_sum;
__device__ float g_valid_cnt;

// ---- 1) reset accumulators + build label bitmasks ----
__global__ void prep_kernel(const float* __restrict__ labels) {
    int i = blockIdx.x * blockDim.x + threadIdx.x;
    if (i == 0) { g_loss_sum = 0.f; g_valid_cnt = 0.f; }
    if (i < BB) {
        const float* lr = labels + (size_t)i * CC;
        unsigned long long m0 = 0ull, m1 = 0ull;
        #pragma unroll
        for (int c = 0; c < 64; c++)
            if (lr[c] != 0.f) m0 |= (1ull << c);
        #pragma unroll
        for (int c = 64; c < CC; c++)
            if (lr[c] != 0.f) m1 |= (1ull << (c - 64));
        g_m[i] = make_ulonglong2(m0, m1);
        g_s[i] = (float)(__popcll(m0) + __popcll(m1));
        g_hardneg[i] = __float_as_uint(1e9f);
    }
}

// ---- 2) L2-normalize rows, record |e|^2 ----
__global__ __launch_bounds__(128) void normalize_kernel(const float* __restrict__ emb) {
    int row = blockIdx.x;
    int t = threadIdx.x;                         // 128 threads, DD/4 = 128 float4
    const float4* in = (const float4*)(emb + (size_t)row * DD);
    float4* out = (float4*)(g_e + (size_t)row * DD);
    float4 v = in[t];
    float ss = v.x * v.x + v.y * v.y + v.z * v.z + v.w * v.w;
    #pragma unroll
    for (int o = 16; o > 0; o >>= 1) ss += __shfl_xor_sync(0xFFFFFFFFu, ss, o);
    __shared__ float red[4];
    if ((t & 31) == 0) red[t >> 5] = ss;
    __syncthreads();
    float tot = red[0] + red[1] + red[2] + red[3];
    float inv = 1.f / fmaxf(sqrtf(tot), 1e-12f);
    v.x *= inv; v.y *= inv; v.z *= inv; v.w *= inv;
    out[t] = v;
    if (t == 0) g_sq[row] = tot * inv * inv;
}

// ---- 3) triangular Gram GEMM + fused epilogue.
//      Only tiles with by <= bx are computed; off-diagonal tiles write both
//      the (i,j) block and its transpose, and update hard-negative mins for
//      both row sets (mask test is symmetric). ----
__global__ __launch_bounds__(256, 1) void gemm_epi_kernel() {
    __shared__ float As[BK][BM];
    __shared__ float Bs[BK][BN];
    __shared__ float s_sqi[BM], s_sqj[BN];
    __shared__ ulonglong2 s_mi[BM], s_mj[BN];

    // triangular tile map: t -> (by <= bx)
    const int t = blockIdx.x;
    int p = (int)((sqrt(8.0 * t + 1.0) - 1.0) * 0.5);
    while ((p * (p + 1)) / 2 > t) p--;
    while (((p + 1) * (p + 2)) / 2 <= t) p++;
    const int bx = p;
    const int by = t - (p * (p + 1)) / 2;
    const bool diag = (bx == by);

    const int tid = threadIdx.x;
    const int tx = tid & 15;
    const int ty = tid >> 4;

    const float* Aptr = g_e + (size_t)by * BM * DD;
    const float* Bptr = g_e + (size_t)bx * BN * DD;

    const int lrow = tid >> 2;          // 0..63
    const int lcol = (tid & 3) << 2;    // 0,4,8,12

    float acc[8][8];
    #pragma unroll
    for (int a = 0; a < 8; a++)
        #pragma unroll
        for (int b = 0; b < 8; b++) acc[a][b] = 0.f;

    for (int k0 = 0; k0 < DD; k0 += BK) {
        float4 a0 = *(const float4*)(Aptr + (size_t)lrow * DD + k0 + lcol);
        float4 a1 = *(const float4*)(Aptr + (size_t)(lrow + 64) * DD + k0 + lcol);
        float4 b0 = *(const float4*)(Bptr + (size_t)lrow * DD + k0 + lcol);
        float4 b1 = *(const float4*)(Bptr + (size_t)(lrow + 64) * DD + k0 + lcol);
        __syncthreads();
        As[lcol + 0][lrow] = a0.x; As[lcol + 1][lrow] = a0.y;
        As[lcol + 2][lrow] = a0.z; As[lcol + 3][lrow] = a0.w;
        As[lcol + 0][lrow + 64] = a1.x; As[lcol + 1][lrow + 64] = a1.y;
        As[lcol + 2][lrow + 64] = a1.z; As[lcol + 3][lrow + 64] = a1.w;
        Bs[lcol + 0][lrow] = b0.x; Bs[lcol + 1][lrow] = b0.y;
        Bs[lcol + 2][lrow] = b0.z; Bs[lcol + 3][lrow] = b0.w;
        Bs[lcol + 0][lrow + 64] = b1.x; Bs[lcol + 1][lrow + 64] = b1.y;
        Bs[lcol + 2][lrow + 64] = b1.z; Bs[lcol + 3][lrow + 64] = b1.w;
        __syncthreads();
        #pragma unroll
        for (int k = 0; k < BK; k++) {
            float ar[8], br[8];
            *(float4*)(ar)     = *(const float4*)(&As[k][ty * 8]);
            *(float4*)(ar + 4) = *(const float4*)(&As[k][ty * 8 + 4]);
            *(float4*)(br)     = *(const float4*)(&Bs[k][tx * 8]);
            *(float4*)(br + 4) = *(const float4*)(&Bs[k][tx * 8 + 4]);
            #pragma unroll
            for (int ii = 0; ii < 8; ii++)
                #pragma unroll
                for (int jj = 0; jj < 8; jj++)
                    acc[ii][jj] = fmaf(ar[ii], br[jj], acc[ii][jj]);
        }
    }

    // stage per-row/col metadata
    __syncthreads();
    if (tid < 128) {
        int gi = by * BM + tid;
        int gj = bx * BN + tid;
        s_sqi[tid] = g_sq[gi];
        s_sqj[tid] = g_sq[gj];
        s_mi[tid] = g_m[gi];
        s_mj[tid] = g_m[gj];
    }
    __syncthreads();

    // convert acc -> distances in place
    #pragma unroll
    for (int ii = 0; ii < 8; ii++) {
        float sqi = s_sqi[ty * 8 + ii];
        #pragma unroll
        for (int jj = 0; jj < 8; jj++) {
            float d2 = sqi + s_sqj[tx * 8 + jj] - 2.f * acc[ii][jj];
            acc[ii][jj] = sqrtf(fmaxf(d2, 0.f));
        }
    }

    // row side: store block (gi rows, gj cols) + hardneg for gi
    #pragma unroll
    for (int ii = 0; ii < 8; ii++) {
        int li = ty * 8 + ii;
        int gi = by * BM + li;
        ulonglong2 mi = s_mi[li];
        float rmin = 1e9f;
        #pragma unroll
        for (int jj = 0; jj < 8; jj++) {
            ulonglong2 mj = s_mj[tx * 8 + jj];
            int inter = __popcll(mi.x & mj.x) + __popcll(mi.y & mj.y);
            if (inter == 0) rmin = fminf(rmin, acc[ii][jj]);
        }
        float* gp = g_dist + (size_t)gi * BB + bx * BN + tx * 8;
        *(float4*)(gp)     = make_float4(acc[ii][0], acc[ii][1], acc[ii][2], acc[ii][3]);
        *(float4*)(gp + 4) = make_float4(acc[ii][4], acc[ii][5], acc[ii][6], acc[ii][7]);
        if (rmin < 1e9f)
            atomicMin(&g_hardneg[gi], __float_as_uint(rmin));
    }

    // column side (off-diagonal tiles only): store transpose + hardneg for gj
    if (!diag) {
        #pragma unroll
        for (int jj = 0; jj < 8; jj++) {
            int lj = tx * 8 + jj;
            int gj = bx * BN + lj;
            ulonglong2 mj = s_mj[lj];
            float cmin = 1e9f;
            #pragma unroll
            for (int ii = 0; ii < 8; ii++) {
                ulonglong2 mi = s_mi[ty * 8 + ii];
                int inter = __popcll(mi.x & mj.x) + __popcll(mi.y & mj.y);
                if (inter == 0) cmin = fminf(cmin, acc[ii][jj]);
            }
            float* gp = g_dist + (size_t)gj * BB + by * BM + ty * 8;
            *(float4*)(gp)     = make_float4(acc[0][jj], acc[1][jj], acc[2][jj], acc[3][jj]);
            *(float4*)(gp + 4) = make_float4(acc[4][jj], acc[5][jj], acc[6][jj], acc[7][jj]);
            if (cmin < 1e9f)
                atomicMin(&g_hardneg[gj], __float_as_uint(cmin));
        }
    }
}

// ---- 4) per-row weighted hinge over positives ----
__global__ __launch_bounds__(256) void rowloss_kernel() {
    const int i = blockIdx.x;
    const int t = threadIdx.x;
    const float h = __uint_as_float(g_hardneg[i]);
    const ulonglong2 mi = g_m[i];
    const float si = g_s[i];
    const float* drow = g_dist + (size_t)i * BB;

    float acc = 0.f;
    int cnt = 0;
    int anyneg = 0;
    for (int j0 = t * 4; j0 < BB; j0 += 256 * 4) {
        float4 d4 = *(const float4*)(drow + j0);
        float dv[4] = {d4.x, d4.y, d4.z, d4.w};
        #pragma unroll
        for (int u = 0; u < 4; u++) {
            int j = j0 + u;
            ulonglong2 mj = g_m[j];
            int inter = __popcll(mi.x & mj.x) + __popcll(mi.y & mj.y);
            if (inter == 0) {
                anyneg = 1;
            } else if (j != i) {
                float jac = (float)inter / (si + g_s[j] - (float)inter + 1e-8f);
                acc += fmaxf(dv[u] - h + MARGIN, 0.f) * jac;
                cnt++;
            }
        }
    }
    #pragma unroll
    for (int o = 16; o > 0; o >>= 1) {
        acc += __shfl_xor_sync(0xFFFFFFFFu, acc, o);
        cnt += __shfl_xor_sync(0xFFFFFFFFu, cnt, o);
        anyneg |= __shfl_xor_sync(0xFFFFFFFFu, anyneg, o);
    }
    __shared__ float sacc[8];
    __shared__ int scnt[8], sneg[8];
    if ((t & 31) == 0) { sacc[t >> 5] = acc; scnt[t >> 5] = cnt; sneg[t >> 5] = anyneg; }
    __syncthreads();
    if (t == 0) {
        float a = 0.f; int c = 0, n = 0;
        #pragma unroll
        for (int w = 0; w < 8; w++) { a += sacc[w]; c += scnt[w]; n |= sneg[w]; }
        if (c > 0 && n) {
            atomicAdd(&g_loss_sum, a / (float)c);
            atomicAdd(&g_valid_cnt, 1.f);
        }
    }
}

// ---- 5) finalize ----
__global__ void finalize_kernel(float* out, int n) {
    if (threadIdx.x == 0 && blockIdx.x == 0) {
        out[0] = g_loss_sum / (g_valid_cnt + 1e-8f);
        for (int k = 1; k < n; k++) out[k] = 0.f;
    }
}

extern "C" void kernel_launch(void* const* d_in, const int* in_sizes, int n_in,
                              void* d_out, int out_size) {
    const float* emb = (const float*)d_in[0];
    const float* labels = (const float*)d_in[1];

    prep_kernel<<<(BB + 255) / 256, 256>>>(labels);
    normalize_kernel<<<BB, 128>>>(emb);
    gemm_epi_kernel<<<NTRI, 256>>>();
    rowloss_kernel<<<BB, 256>>>();
    finalize_kernel<<<1, 32>>>((float*)d_out, out_size);
}

// round 5
// speedup vs baseline: 4.5725x; 3.0397x over previous
#include <cuda_runtime.h>
#include <cuda_bf16.h>
#include <cstdint>
#include <math.h>

#define BB 8192
#define DD 512
#define CC 80
#define MARGIN 0.3f

#define BM 128
#define NTILE (BB / BM)                  // 64
#define NTRI  (NTILE * (NTILE + 1) / 2)  // 2080
#define BK 32                            // bf16 K-chunk
#define NCH (DD / BK)                    // 16

// smem layout (bytes)
#define RSB   80                         // padded row stride (32 bf16 + 8 pad)
#define OPB   (128 * RSB)                // 10240 per operand
#define BUFB  (4 * OPB)                  // 40960 per buffer (Ah,Al,Bh,Bl)
#define SM_SQI 81920
#define SM_SQJ 82432
#define SM_MI  82944
#define SM_MJ  84992
#define SM_TOT 87040                     // sD[128*129 floats]=66048 overlays buffers

// ---- device scratch ----
__device__ __nv_bfloat16 g_eh[(size_t)BB * DD];
__device__ __nv_bfloat16 g_el[(size_t)BB * DD];
__device__ float g_sq[BB];
__device__ ulonglong2 g_m[BB];
__device__ float g_s[BB];
__device__ float g_dist[(size_t)BB * BB];
__device__ unsigned g_hardneg[BB];
__device__ float g_loss_sum;
__device__ float g_valid_cnt;

// ---- PTX helpers (baseline ISA only; no 'a'-suffix features) ----
__device__ __forceinline__ uint32_t smem_u32(const void* p) {
    uint32_t a;
    asm("{ .reg .u64 t; cvta.to.shared.u64 t, %1; cvt.u32.u64 %0, t; }" : "=r"(a) : "l"(p));
    return a;
}
#define CP_ASYNC16(dst, src) \
    asm volatile("cp.async.cg.shared.global [%0], [%1], 16;" :: "r"(dst), "l"(src))
#define CP_COMMIT() asm volatile("cp.async.commit_group;" ::: "memory")
#define CP_WAIT1()  asm volatile("cp.async.wait_group 1;" ::: "memory")
#define CP_WAIT0()  asm volatile("cp.async.wait_group 0;" ::: "memory")

#define LDSM_X4(r, a) \
    asm volatile("ldmatrix.sync.aligned.m8n8.x4.shared.b16 {%0,%1,%2,%3}, [%4];" \
        : "=r"((r)[0]), "=r"((r)[1]), "=r"((r)[2]), "=r"((r)[3]) : "r"(a))
#define LDSM_X2(r, a) \
    asm volatile("ldmatrix.sync.aligned.m8n8.x2.shared.b16 {%0,%1}, [%2];" \
        : "=r"((r)[0]), "=r"((r)[1]) : "r"(a))
#define MMA16816(d, a, b) \
    asm volatile("mma.sync.aligned.m16n8k16.row.col.f32.bf16.bf16.f32 " \
        "{%0,%1,%2,%3}, {%4,%5,%6,%7}, {%8,%9}, {%0,%1,%2,%3};" \
        : "+f"((d)[0]), "+f"((d)[1]), "+f"((d)[2]), "+f"((d)[3]) \
        : "r"((a)[0]), "r"((a)[1]), "r"((a)[2]), "r"((a)[3]), "r"((b)[0]), "r"((b)[1]))

// ---- 1) reset accumulators + label bitmasks ----
__global__ void prep_kernel(const float* __restrict__ labels) {
    int i = blockIdx.x * blockDim.x + threadIdx.x;
    if (i == 0) { g_loss_sum = 0.f; g_valid_cnt = 0.f; }
    if (i < BB) {
        const float* lr = labels + (size_t)i * CC;
        unsigned long long m0 = 0ull, m1 = 0ull;
        #pragma unroll
        for (int c = 0; c < 64; c++)
            if (lr[c] != 0.f) m0 |= (1ull << c);
        #pragma unroll
        for (int c = 64; c < CC; c++)
            if (lr[c] != 0.f) m1 |= (1ull << (c - 64));
        g_m[i] = make_ulonglong2(m0, m1);
        g_s[i] = (float)(__popcll(m0) + __popcll(m1));
        g_hardneg[i] = __float_as_uint(1e9f);
    }
}

// ---- 2) normalize + bf16 split (e = hi + lo) ----
__global__ __launch_bounds__(128) void normalize_kernel(const float* __restrict__ emb) {
    int row = blockIdx.x;
    int t = threadIdx.x;
    const float4* in = (const float4*)(emb + (size_t)row * DD);
    float4 v = in[t];
    float ss = v.x * v.x + v.y * v.y + v.z * v.z + v.w * v.w;
    #pragma unroll
    for (int o = 16; o > 0; o >>= 1) ss += __shfl_xor_sync(0xFFFFFFFFu, ss, o);
    __shared__ float red[4];
    if ((t & 31) == 0) red[t >> 5] = ss;
    __syncthreads();
    float tot = red[0] + red[1] + red[2] + red[3];
    float inv = 1.f / fmaxf(sqrtf(tot), 1e-12f);
    float e[4] = {v.x * inv, v.y * inv, v.z * inv, v.w * inv};
    __nv_bfloat16 hh[4], ll[4];
    #pragma unroll
    for (int u = 0; u < 4; u++) {
        hh[u] = __float2bfloat16_rn(e[u]);
        ll[u] = __float2bfloat16_rn(e[u] - __bfloat162float(hh[u]));
    }
    size_t base = (size_t)row * DD + t * 4;
    *(uint2*)(g_eh + base) = *(uint2*)hh;
    *(uint2*)(g_el + base) = *(uint2*)ll;
    if (t == 0) g_sq[row] = tot * inv * inv;
}

// ---- 3) bf16-split mma.sync Gram GEMM over triangular tiles + fused epilogue ----
__global__ __launch_bounds__(256, 2) void gemm_tc_kernel() {
    extern __shared__ __align__(1024) char smem[];
    const uint32_t sb = smem_u32(smem);
    const int tid = threadIdx.x;
    const int wid = tid >> 5;
    const int lane = tid & 31;
    const int wm = wid >> 2;         // 0..1 -> rows wm*64
    const int wn = wid & 3;          // 0..3 -> cols wn*32

    // triangular tile map (by <= bx)
    const int t = blockIdx.x;
    int p = (int)((sqrt(8.0 * t + 1.0) - 1.0) * 0.5);
    while ((p * (p + 1)) / 2 > t) p--;
    while (((p + 1) * (p + 2)) / 2 <= t) p++;
    const int bx = p;
    const int by = t - (p * (p + 1)) / 2;
    const bool diag = (bx == by);

    // stage per-row/col metadata (region disjoint from pipeline buffers)
    if (tid < 128) {
        int gi = by * BM + tid, gj = bx * BM + tid;
        ((float*)(smem + SM_SQI))[tid] = g_sq[gi];
        ((float*)(smem + SM_SQJ))[tid] = g_sq[gj];
        ((ulonglong2*)(smem + SM_MI))[tid] = g_m[gi];
        ((ulonglong2*)(smem + SM_MJ))[tid] = g_m[gj];
    }

    // operand group for loading: 0=Ah 1=Al 2=Bh 3=Bl, 64 threads each
    const int opg = tid >> 6;
    const int t64 = tid & 63;
    const __nv_bfloat16* srcbase = (opg == 0 || opg == 2) ? g_eh : g_el;
    const int rowbase = ((opg < 2) ? by : bx) * BM;
    const char* src_tile = (const char*)srcbase + (size_t)rowbase * (DD * 2);

    float acc[4][4][4];
    #pragma unroll
    for (int a = 0; a < 4; a++)
        #pragma unroll
        for (int b = 0; b < 4; b++)
            #pragma unroll
            for (int e = 0; e < 4; e++) acc[a][b][e] = 0.f;

    // chunk loader: 8 x 16B per thread, coalesced (4 threads cover a 64B row)
    auto load_chunk = [&](int c, int buf) {
        uint32_t dst0 = sb + buf * BUFB + opg * OPB;
        const char* src0 = src_tile + c * (BK * 2);
        #pragma unroll
        for (int s = 0; s < 8; s++) {
            int g = s * 64 + t64;
            int row = g >> 2, sg = g & 3;
            CP_ASYNC16(dst0 + row * RSB + sg * 16, src0 + (size_t)row * (DD * 2) + sg * 16);
        }
    };

    auto compute_chunk = [&](int buf) {
        const uint32_t ahb = sb + buf * BUFB;
        const uint32_t alb = ahb + OPB;
        const uint32_t bhb = ahb + 2 * OPB;
        const uint32_t blb = ahb + 3 * OPB;
        const int l16 = lane & 15;
        #pragma unroll
        for (int ks = 0; ks < 2; ks++) {
            uint32_t ah[4][4], al[4][4], bb[4][2];
            const int aoff = (wm * 64 + (lane & 15)) * RSB + ks * 32 + (lane >> 4) * 16;
            #pragma unroll
            for (int mt = 0; mt < 4; mt++) {
                LDSM_X4(ah[mt], ahb + aoff + mt * 16 * RSB);
                LDSM_X4(al[mt], alb + aoff + mt * 16 * RSB);
            }
            const int boff = (wn * 32 + (l16 & 7)) * RSB + ks * 32 + (l16 >> 3) * 16;
            #pragma unroll
            for (int nt = 0; nt < 4; nt++) LDSM_X2(bb[nt], bhb + boff + nt * 8 * RSB);
            #pragma unroll
            for (int mt = 0; mt < 4; mt++)
                #pragma unroll
                for (int nt = 0; nt < 4; nt++) MMA16816(acc[mt][nt], ah[mt], bb[nt]);
            #pragma unroll
            for (int mt = 0; mt < 4; mt++)
                #pragma unroll
                for (int nt = 0; nt < 4; nt++) MMA16816(acc[mt][nt], al[mt], bb[nt]);
            #pragma unroll
            for (int nt = 0; nt < 4; nt++) LDSM_X2(bb[nt], blb + boff + nt * 8 * RSB);
            #pragma unroll
            for (int mt = 0; mt < 4; mt++)
                #pragma unroll
                for (int nt = 0; nt < 4; nt++) MMA16816(acc[mt][nt], ah[mt], bb[nt]);
        }
    };

    load_chunk(0, 0);
    CP_COMMIT();
    for (int c = 0; c < NCH; c++) {
        const int buf = c & 1;
        if (c + 1 < NCH) { load_chunk(c + 1, buf ^ 1); CP_COMMIT(); CP_WAIT1(); }
        else CP_WAIT0();
        __syncthreads();
        compute_chunk(buf);
        __syncthreads();
    }

    // ---- epilogue: dist + hard-neg mins + staged global writes ----
    float* sD = (float*)smem;    // [128][129], overlays buffers (done with them)
    const float* sqi = (const float*)(smem + SM_SQI);
    const float* sqj = (const float*)(smem + SM_SQJ);
    const ulonglong2* smi = (const ulonglong2*)(smem + SM_MI);
    const ulonglong2* smj = (const ulonglong2*)(smem + SM_MJ);

    float rmin[4][2], cmin[4][2];
    #pragma unroll
    for (int a = 0; a < 4; a++) { rmin[a][0] = rmin[a][1] = 1e9f; cmin[a][0] = cmin[a][1] = 1e9f; }

    #pragma unroll
    for (int mt = 0; mt < 4; mt++)
        #pragma unroll
        for (int nt = 0; nt < 4; nt++)
            #pragma unroll
            for (int e = 0; e < 4; e++) {
                int m = wm * 64 + mt * 16 + (lane >> 2) + (e >> 1) * 8;
                int n = wn * 32 + nt * 8 + (lane & 3) * 2 + (e & 1);
                float d2 = sqi[m] + sqj[n] - 2.f * acc[mt][nt][e];
                float d = sqrtf(fmaxf(d2, 0.f));
                sD[m * 129 + n] = d;
                ulonglong2 ma = smi[m], mb = smj[n];
                int inter = __popcll(ma.x & mb.x) + __popcll(ma.y & mb.y);
                if (inter == 0) {
                    rmin[mt][e >> 1] = fminf(rmin[mt][e >> 1], d);
                    cmin[nt][e & 1] = fminf(cmin[nt][e & 1], d);
                }
            }

    // row-side hard-neg: reduce over lane&3 (same m)
    #pragma unroll
    for (int mt = 0; mt < 4; mt++)
        #pragma unroll
        for (int hh = 0; hh < 2; hh++) {
            float v = rmin[mt][hh];
            v = fminf(v, __shfl_xor_sync(0xFFFFFFFFu, v, 1));
            v = fminf(v, __shfl_xor_sync(0xFFFFFFFFu, v, 2));
            if ((lane & 3) == 0 && v < 1e9f) {
                int m = wm * 64 + mt * 16 + (lane >> 2) + hh * 8;
                atomicMin(&g_hardneg[by * BM + m], __float_as_uint(v));
            }
        }
    // col-side hard-neg (off-diagonal only): reduce over lane>>2 (same n)
    if (!diag) {
        #pragma unroll
        for (int nt = 0; nt < 4; nt++)
            #pragma unroll
            for (int b2 = 0; b2 < 2; b2++) {
                float v = cmin[nt][b2];
                v = fminf(v, __shfl_xor_sync(0xFFFFFFFFu, v, 4));
                v = fminf(v, __shfl_xor_sync(0xFFFFFFFFu, v, 8));
                v = fminf(v, __shfl_xor_sync(0xFFFFFFFFu, v, 16));
                if (lane < 4 && v < 1e9f) {
                    int n = wn * 32 + nt * 8 + (lane & 3) * 2 + b2;
                    atomicMin(&g_hardneg[bx * BM + n], __float_as_uint(v));
                }
            }
    }

    __syncthreads();
    const int cl = tid & 127;
    const int rh = tid >> 7;
    #pragma unroll 4
    for (int r2 = 0; r2 < 64; r2++) {
        int r = r2 * 2 + rh;
        g_dist[(size_t)(by * BM + r) * BB + bx * BM + cl] = sD[r * 129 + cl];
    }
    if (!diag) {
        #pragma unroll 4
        for (int r2 = 0; r2 < 64; r2++) {
            int c2 = r2 * 2 + rh;
            g_dist[(size_t)(bx * BM + c2) * BB + by * BM + cl] = sD[cl * 129 + c2];
        }
    }
}

// ---- 4) per-row weighted hinge over positives (4 anchors per block) ----
__global__ __launch_bounds__(256) void rowloss_kernel() {
    const int i0 = blockIdx.x * 4;
    const int t = threadIdx.x;
    float h[4], si[4];
    ulonglong2 mi[4];
    #pragma unroll
    for (int a = 0; a < 4; a++) {
        h[a] = __uint_as_float(g_hardneg[i0 + a]);
        mi[a] = g_m[i0 + a];
        si[a] = g_s[i0 + a];
    }
    float acc[4] = {0.f, 0.f, 0.f, 0.f};
    int cnt[4] = {0, 0, 0, 0};
    int ang[4] = {0, 0, 0, 0};

    for (int j0 = t * 4; j0 < BB; j0 += 1024) {
        ulonglong2 mj[4];
        #pragma unroll
        for (int u = 0; u < 4; u++) mj[u] = g_m[j0 + u];
        float4 sj4 = *(const float4*)(g_s + j0);
        float sj[4] = {sj4.x, sj4.y, sj4.z, sj4.w};
        #pragma unroll
        for (int a = 0; a < 4; a++) {
            float4 d4 = *(const float4*)(g_dist + (size_t)(i0 + a) * BB + j0);
            float dv[4] = {d4.x, d4.y, d4.z, d4.w};
            #pragma unroll
            for (int u = 0; u < 4; u++) {
                int inter = __popcll(mi[a].x & mj[u].x) + __popcll(mi[a].y & mj[u].y);
                if (inter == 0) {
                    ang[a] = 1;
                } else if (j0 + u != i0 + a) {
                    float jac = __fdividef((float)inter, si[a] + sj[u] - (float)inter + 1e-8f);
                    acc[a] += fmaxf(dv[u] - h[a] + MARGIN, 0.f) * jac;
                    cnt[a]++;
                }
            }
        }
    }

    #pragma unroll
    for (int a = 0; a < 4; a++)
        #pragma unroll
        for (int o = 16; o > 0; o >>= 1) {
            acc[a] += __shfl_xor_sync(0xFFFFFFFFu, acc[a], o);
            cnt[a] += __shfl_xor_sync(0xFFFFFFFFu, cnt[a], o);
            ang[a] |= __shfl_xor_sync(0xFFFFFFFFu, ang[a], o);
        }
    __shared__ float sacc[8][4];
    __shared__ int scnt[8][4], sneg[8][4];
    if ((t & 31) == 0) {
        #pragma unroll
        for (int a = 0; a < 4; a++) {
            sacc[t >> 5][a] = acc[a];
            scnt[t >> 5][a] = cnt[a];
            sneg[t >> 5][a] = ang[a];
        }
    }
    __syncthreads();
    if (t < 4) {
        float av = 0.f; int c = 0, n = 0;
        #pragma unroll
        for (int w = 0; w < 8; w++) { av += sacc[w][t]; c += scnt[w][t]; n |= sneg[w][t]; }
        if (c > 0 && n) {
            atomicAdd(&g_loss_sum, av / (float)c);
            atomicAdd(&g_valid_cnt, 1.f);
        }
    }
}

// ---- 5) finalize ----
__global__ void finalize_kernel(float* out, int n) {
    if (threadIdx.x == 0 && blockIdx.x == 0) {
        out[0] = g_loss_sum / (g_valid_cnt + 1e-8f);
        for (int k = 1; k < n; k++) out[k] = 0.f;
    }
}

extern "C" void kernel_launch(void* const* d_in, const int* in_sizes, int n_in,
                              void* d_out, int out_size) {
    const float* emb = (const float*)d_in[0];
    const float* labels = (const float*)d_in[1];

    static int configured = 0;
    if (!configured) {
        cudaFuncSetAttribute(gemm_tc_kernel,
                             cudaFuncAttributeMaxDynamicSharedMemorySize, SM_TOT);
        configured = 1;
    }

    prep_kernel<<<(BB + 255) / 256, 256>>>(labels);
    normalize_kernel<<<BB, 128>>>(emb);
    gemm_tc_kernel<<<NTRI, 256, SM_TOT>>>();
    rowloss_kernel<<<BB / 4, 256>>>();
    finalize_kernel<<<1, 32>>>((float*)d_out, out_size);
}